// round 4
// baseline (speedup 1.0000x reference)
#include <cuda_runtime.h>
#include <cuda_bf16.h>
#include <cstdint>

// x[N=32768, D=2048] fp32 row-major.
// u[d] = sum_n x[n][d]^2 + eps ; out = x * rsqrt(u)

#define NROWS 32768
#define NCOLS 2048
#define NCOLS4 (NCOLS / 4)                     // 512 float4 column-groups
#define ROWS_PER_CHUNK 64
#define ROW_CHUNKS (NROWS / ROWS_PER_CHUNK)    // 512
#define SPLITS 32
#define CHUNKS_PER_SPLIT (ROW_CHUNKS / SPLITS) // 16
#define EPS 1e-6f

// Deterministic scratch (no atomics anywhere)
__device__ float g_part [ROW_CHUNKS * NCOLS];  // 4 MB
__device__ float g_part2[SPLITS * NCOLS];      // 256 KB
__device__ float g_scale[NCOLS];               // 8 KB

// ---------------------------------------------------------------------------
// K1: per-row-chunk column sum of squares.
// grid = (2, 512) -> 1024 CTAs (~7/SM). Each thread owns one float4 column
// group for 64 rows; unroll 16 -> 16 independent LDG.128 in flight.
// ---------------------------------------------------------------------------
__global__ void __launch_bounds__(256) colsq_kernel(const float4* __restrict__ x) {
    const int cg    = blockIdx.x * 256 + threadIdx.x;   // 0..511
    const int chunk = blockIdx.y;                        // 0..511

    const float4* p = x + (size_t)chunk * ROWS_PER_CHUNK * NCOLS4 + cg;

    float ax = 0.f, ay = 0.f, az = 0.f, aw = 0.f;
#pragma unroll 16
    for (int r = 0; r < ROWS_PER_CHUNK; ++r) {
        float4 v = __ldg(p + (size_t)r * NCOLS4);
        ax = fmaf(v.x, v.x, ax);
        ay = fmaf(v.y, v.y, ay);
        az = fmaf(v.z, v.z, az);
        aw = fmaf(v.w, v.w, aw);
    }

    reinterpret_cast<float4*>(g_part)[(size_t)chunk * NCOLS4 + cg] =
        make_float4(ax, ay, az, aw);
}

// ---------------------------------------------------------------------------
// K2a: fold 512 chunk-partials -> 32 split-partials. Coalesced float4.
// ---------------------------------------------------------------------------
__global__ void __launch_bounds__(256) reduceA_kernel() {
    const int cg    = blockIdx.x * 256 + threadIdx.x;   // 0..511
    const int split = blockIdx.y;                        // 0..31

    const float4* p = reinterpret_cast<const float4*>(g_part)
                    + (size_t)split * CHUNKS_PER_SPLIT * NCOLS4 + cg;
    float4 a = make_float4(0.f, 0.f, 0.f, 0.f);
#pragma unroll
    for (int k = 0; k < CHUNKS_PER_SPLIT; ++k) {
        float4 v = p[(size_t)k * NCOLS4];
        a.x += v.x; a.y += v.y; a.z += v.z; a.w += v.w;
    }
    reinterpret_cast<float4*>(g_part2)[(size_t)split * NCOLS4 + cg] = a;
}

// ---------------------------------------------------------------------------
// K2b: fold 32 split-partials, rsqrt -> scale. 512 threads, float4.
// ---------------------------------------------------------------------------
__global__ void __launch_bounds__(256) reduceB_kernel() {
    const int cg = blockIdx.x * 256 + threadIdx.x;       // 0..511
    const float4* p = reinterpret_cast<const float4*>(g_part2) + cg;
    float4 a = make_float4(0.f, 0.f, 0.f, 0.f);
#pragma unroll
    for (int k = 0; k < SPLITS; ++k) {
        float4 v = p[(size_t)k * NCOLS4];
        a.x += v.x; a.y += v.y; a.z += v.z; a.w += v.w;
    }
    float4 s;
    s.x = rsqrtf(a.x + EPS);
    s.y = rsqrtf(a.y + EPS);
    s.z = rsqrtf(a.z + EPS);
    s.w = rsqrtf(a.w + EPS);
    reinterpret_cast<float4*>(g_scale)[cg] = s;
}

// ---------------------------------------------------------------------------
// K3: out = x * scale[col]. 4 float4 per thread, loads batched before stores
// (front MLP=4). Reverse block order (free; any L2 tail hit is gravy).
// Streaming stores only on the 256MB output.
// ---------------------------------------------------------------------------
#define FL4_TOTAL (NROWS * NCOLS4)             // 16M float4
#define FL4_PER_BLOCK 1024
#define K3_BLOCKS (FL4_TOTAL / FL4_PER_BLOCK)  // 16384

__global__ void __launch_bounds__(256) scale_kernel(const float4* __restrict__ x,
                                                    float4* __restrict__ out) {
    const int blk     = K3_BLOCKS - 1 - blockIdx.x;       // reversed
    const size_t base = (size_t)blk * FL4_PER_BLOCK + threadIdx.x;

    // Batch the 4 independent global loads first.
    float4 v0 = x[base];
    float4 v1 = x[base + 256];
    float4 v2 = x[base + 512];
    float4 v3 = x[base + 768];

    const int cg0 = (int)( base        & (NCOLS4 - 1));
    const int cg1 = (int)((base + 256) & (NCOLS4 - 1));
    const int cg2 = (int)((base + 512) & (NCOLS4 - 1));
    const int cg3 = (int)((base + 768) & (NCOLS4 - 1));

    const float4* sc = reinterpret_cast<const float4*>(g_scale);
    float4 s0 = __ldg(sc + cg0);
    float4 s1 = __ldg(sc + cg1);
    float4 s2 = __ldg(sc + cg2);
    float4 s3 = __ldg(sc + cg3);

    v0.x *= s0.x; v0.y *= s0.y; v0.z *= s0.z; v0.w *= s0.w;
    v1.x *= s1.x; v1.y *= s1.y; v1.z *= s1.z; v1.w *= s1.w;
    v2.x *= s2.x; v2.y *= s2.y; v2.z *= s2.z; v2.w *= s2.w;
    v3.x *= s3.x; v3.y *= s3.y; v3.z *= s3.z; v3.w *= s3.w;

    __stcs(out + base,       v0);
    __stcs(out + base + 256, v1);
    __stcs(out + base + 512, v2);
    __stcs(out + base + 768, v3);
}

// ---------------------------------------------------------------------------
extern "C" void kernel_launch(void* const* d_in, const int* in_sizes, int n_in,
                              void* d_out, int out_size) {
    const float4* x   = reinterpret_cast<const float4*>(d_in[0]);
    float4*       out = reinterpret_cast<float4*>(d_out);

    colsq_kernel  <<<dim3(2, ROW_CHUNKS), 256>>>(x);
    reduceA_kernel<<<dim3(2, SPLITS), 256>>>();
    reduceB_kernel<<<2, 256>>>();
    scale_kernel  <<<K3_BLOCKS, 256>>>(x, out);
}

// round 6
// speedup vs baseline: 1.1031x; 1.1031x over previous
#include <cuda_runtime.h>
#include <cuda_bf16.h>
#include <cstdint>

// x[N=32768, D=2048] fp32 row-major.
// u[d] = sum_n x[n][d]^2 + eps ; out = x * rsqrt(u)

#define NROWS 32768
#define NCOLS 2048
#define NCOLS4 (NCOLS / 4)                     // 512 float4 column-groups
#define ROWS_PER_CHUNK 32
#define ROW_CHUNKS (NROWS / ROWS_PER_CHUNK)    // 1024
#define KEEP_CHUNK 640                         // tail chunks cached normally
#define SPLITS 32
#define CHUNKS_PER_SPLIT (ROW_CHUNKS / SPLITS) // 32
#define EPS 1e-6f

// Deterministic scratch (no atomics anywhere)
__device__ float g_part [ROW_CHUNKS * NCOLS];  // 8 MB
__device__ float g_part2[SPLITS * NCOLS];      // 256 KB
__device__ float g_scale[NCOLS];               // 8 KB

// ---------------------------------------------------------------------------
// K1: per-row-chunk column sum of squares. grid = (2, 1024), 32 rows/chunk.
// (R3 config — best measured "rest" time.)
// ---------------------------------------------------------------------------
__global__ void __launch_bounds__(256) colsq_kernel(const float4* __restrict__ x) {
    const int cg    = blockIdx.x * 256 + threadIdx.x;   // 0..511
    const int chunk = blockIdx.y;                        // 0..1023

    const float4* p = x + (size_t)chunk * ROWS_PER_CHUNK * NCOLS4 + cg;

    float ax = 0.f, ay = 0.f, az = 0.f, aw = 0.f;
    if (chunk < KEEP_CHUNK) {
#pragma unroll 8
        for (int r = 0; r < ROWS_PER_CHUNK; ++r) {
            float4 v = __ldcs(p + (size_t)r * NCOLS4);
            ax = fmaf(v.x, v.x, ax);
            ay = fmaf(v.y, v.y, ay);
            az = fmaf(v.z, v.z, az);
            aw = fmaf(v.w, v.w, aw);
        }
    } else {
#pragma unroll 8
        for (int r = 0; r < ROWS_PER_CHUNK; ++r) {
            float4 v = __ldg(p + (size_t)r * NCOLS4);
            ax = fmaf(v.x, v.x, ax);
            ay = fmaf(v.y, v.y, ay);
            az = fmaf(v.z, v.z, az);
            aw = fmaf(v.w, v.w, aw);
        }
    }

    reinterpret_cast<float4*>(g_part)[(size_t)chunk * NCOLS4 + cg] =
        make_float4(ax, ay, az, aw);
}

// ---------------------------------------------------------------------------
// K2a: fold 1024 chunk-partials -> 32 split-partials. float4 coalesced.
// ---------------------------------------------------------------------------
__global__ void __launch_bounds__(256) reduceA_kernel() {
    const int cg    = blockIdx.x * 256 + threadIdx.x;   // 0..511
    const int split = blockIdx.y;                        // 0..31

    const float4* p = reinterpret_cast<const float4*>(g_part)
                    + (size_t)split * CHUNKS_PER_SPLIT * NCOLS4 + cg;
    float4 a = make_float4(0.f, 0.f, 0.f, 0.f);
#pragma unroll
    for (int k = 0; k < CHUNKS_PER_SPLIT; ++k) {
        float4 v = p[(size_t)k * NCOLS4];
        a.x += v.x; a.y += v.y; a.z += v.z; a.w += v.w;
    }
    reinterpret_cast<float4*>(g_part2)[(size_t)split * NCOLS4 + cg] = a;
}

// ---------------------------------------------------------------------------
// K2b: fold 32 split-partials, rsqrt -> scale. 512 threads, float4.
// ---------------------------------------------------------------------------
__global__ void __launch_bounds__(256) reduceB_kernel() {
    const int cg = blockIdx.x * 256 + threadIdx.x;       // 0..511
    const float4* p = reinterpret_cast<const float4*>(g_part2) + cg;
    float4 a = make_float4(0.f, 0.f, 0.f, 0.f);
#pragma unroll
    for (int k = 0; k < SPLITS; ++k) {
        float4 v = p[(size_t)k * NCOLS4];
        a.x += v.x; a.y += v.y; a.z += v.z; a.w += v.w;
    }
    float4 s;
    s.x = rsqrtf(a.x + EPS);
    s.y = rsqrtf(a.y + EPS);
    s.z = rsqrtf(a.z + EPS);
    s.w = rsqrtf(a.w + EPS);
    reinterpret_cast<float4*>(g_scale)[cg] = s;
}

// ---------------------------------------------------------------------------
// K3: out = x * scale[col]. R2's exact form — simple 4-iter loop, plain
// cached loads, streaming stores, reversed block order. Best measured: 74.5us.
// ---------------------------------------------------------------------------
#define FL4_TOTAL (NROWS * NCOLS4)             // 16M float4
#define FL4_PER_BLOCK 1024
#define K3_BLOCKS (FL4_TOTAL / FL4_PER_BLOCK)  // 16384

__global__ void __launch_bounds__(256) scale_kernel(const float4* __restrict__ x,
                                                    float4* __restrict__ out) {
    const int blk     = K3_BLOCKS - 1 - blockIdx.x;       // reversed
    const size_t base = (size_t)blk * FL4_PER_BLOCK + threadIdx.x;

#pragma unroll
    for (int it = 0; it < 4; ++it) {
        const size_t i  = base + (size_t)it * 256;
        const int    cg = (int)(i & (NCOLS4 - 1));         // NCOLS4=512 pow2

        float4 s = __ldg(reinterpret_cast<const float4*>(g_scale) + cg);
        float4 v = x[i];
        v.x *= s.x; v.y *= s.y; v.z *= s.z; v.w *= s.w;
        __stcs(out + i, v);
    }
}

// ---------------------------------------------------------------------------
extern "C" void kernel_launch(void* const* d_in, const int* in_sizes, int n_in,
                              void* d_out, int out_size) {
    const float4* x   = reinterpret_cast<const float4*>(d_in[0]);
    float4*       out = reinterpret_cast<float4*>(d_out);

    colsq_kernel  <<<dim3(2, ROW_CHUNKS), 256>>>(x);
    reduceA_kernel<<<dim3(2, SPLITS), 256>>>();
    reduceB_kernel<<<2, 256>>>();
    scale_kernel  <<<K3_BLOCKS, 256>>>(x, out);
}

// round 10
// speedup vs baseline: 1.1037x; 1.0005x over previous
#include <cuda_runtime.h>
#include <cuda_bf16.h>
#include <cstdint>

// x[N=32768, D=2048] fp32 row-major.
// u[d] = sum_n x[n][d]^2 + eps ; out = x * rsqrt(u)
//
// 3 launches: colsq -> reduce(+rsqrt) -> scale. (Persistent/fused variant
// abandoned: unbenchable under the harness despite working logic.)

#define NROWS 32768
#define NCOLS 2048
#define NCOLS4 512                             // float4 column-groups per row
#define ROWS_PER_CHUNK 32
#define ROW_CHUNKS (NROWS / ROWS_PER_CHUNK)    // 1024
#define KEEP_CHUNK 640                         // tail chunks cached normally
#define EPS 1e-6f

// Deterministic scratch (no atomics anywhere)
__device__ float g_part [ROW_CHUNKS * NCOLS];  // 8 MB
__device__ float g_scale[NCOLS];               // 8 KB

// ---------------------------------------------------------------------------
// K1: per-row-chunk column sum of squares. grid = (2, 1024), 32 rows/chunk.
// (R6/R3 measured-best config.)
// ---------------------------------------------------------------------------
__global__ void __launch_bounds__(256) colsq_kernel(const float4* __restrict__ x) {
    const int cg    = blockIdx.x * 256 + threadIdx.x;   // 0..511
    const int chunk = blockIdx.y;                        // 0..1023

    const float4* p = x + (size_t)chunk * ROWS_PER_CHUNK * NCOLS4 + cg;

    float ax = 0.f, ay = 0.f, az = 0.f, aw = 0.f;
    if (chunk < KEEP_CHUNK) {
#pragma unroll 8
        for (int r = 0; r < ROWS_PER_CHUNK; ++r) {
            float4 v = __ldcs(p + (size_t)r * NCOLS4);
            ax = fmaf(v.x, v.x, ax);
            ay = fmaf(v.y, v.y, ay);
            az = fmaf(v.z, v.z, az);
            aw = fmaf(v.w, v.w, aw);
        }
    } else {
#pragma unroll 8
        for (int r = 0; r < ROWS_PER_CHUNK; ++r) {
            float4 v = __ldg(p + (size_t)r * NCOLS4);
            ax = fmaf(v.x, v.x, ax);
            ay = fmaf(v.y, v.y, ay);
            az = fmaf(v.z, v.z, az);
            aw = fmaf(v.w, v.w, aw);
        }
    }

    reinterpret_cast<float4*>(g_part)[(size_t)chunk * NCOLS4 + cg] =
        make_float4(ax, ay, az, aw);
}

// ---------------------------------------------------------------------------
// K2: single-stage fold of 1024 chunk-partials -> scale.
// 64 CTAs x 256 thr = 512 warps; each warp owns one float4 column-group,
// lane-strided over the 1024 chunks (L2-resident, coalesced across lanes:
// 32 lanes read 32 consecutive rows of the same column -> 32 distinct
// 16B segments, fine). Butterfly reduce, lane 0 writes rsqrt.
// ---------------------------------------------------------------------------
__global__ void __launch_bounds__(256) reduce_kernel() {
    const int cg   = blockIdx.x * 8 + (threadIdx.x >> 5);  // 0..511
    const int lane = threadIdx.x & 31;

    const float4* pp = reinterpret_cast<const float4*>(g_part);
    float4 a = make_float4(0.f, 0.f, 0.f, 0.f);
#pragma unroll 8
    for (int k = lane; k < ROW_CHUNKS; k += 32) {
        float4 v = pp[(size_t)k * NCOLS4 + cg];
        a.x += v.x; a.y += v.y; a.z += v.z; a.w += v.w;
    }
#pragma unroll
    for (int off = 16; off > 0; off >>= 1) {
        a.x += __shfl_xor_sync(0xffffffffu, a.x, off);
        a.y += __shfl_xor_sync(0xffffffffu, a.y, off);
        a.z += __shfl_xor_sync(0xffffffffu, a.z, off);
        a.w += __shfl_xor_sync(0xffffffffu, a.w, off);
    }
    if (lane == 0) {
        float4 s;
        s.x = rsqrtf(a.x + EPS);
        s.y = rsqrtf(a.y + EPS);
        s.z = rsqrtf(a.z + EPS);
        s.w = rsqrtf(a.w + EPS);
        reinterpret_cast<float4*>(g_scale)[cg] = s;
    }
}

// ---------------------------------------------------------------------------
// K3: out = x * scale[col]. R2/R6's exact measured-best form — simple
// 4-iter loop, plain cached loads, streaming stores, reversed block order.
// ---------------------------------------------------------------------------
#define FL4_TOTAL (NROWS * NCOLS4)             // 16M float4
#define FL4_PER_BLOCK 1024
#define K3_BLOCKS (FL4_TOTAL / FL4_PER_BLOCK)  // 16384

__global__ void __launch_bounds__(256) scale_kernel(const float4* __restrict__ x,
                                                    float4* __restrict__ out) {
    const int blk     = K3_BLOCKS - 1 - blockIdx.x;       // reversed
    const size_t base = (size_t)blk * FL4_PER_BLOCK + threadIdx.x;

#pragma unroll
    for (int it = 0; it < 4; ++it) {
        const size_t i  = base + (size_t)it * 256;
        const int    cg = (int)(i & (NCOLS4 - 1));         // NCOLS4=512 pow2

        float4 s = __ldg(reinterpret_cast<const float4*>(g_scale) + cg);
        float4 v = x[i];
        v.x *= s.x; v.y *= s.y; v.z *= s.z; v.w *= s.w;
        __stcs(out + i, v);
    }
}

// ---------------------------------------------------------------------------
extern "C" void kernel_launch(void* const* d_in, const int* in_sizes, int n_in,
                              void* d_out, int out_size) {
    const float4* x   = reinterpret_cast<const float4*>(d_in[0]);
    float4*       out = reinterpret_cast<float4*>(d_out);

    colsq_kernel <<<dim3(2, ROW_CHUNKS), 256>>>(x);
    reduce_kernel<<<64, 256>>>();
    scale_kernel <<<K3_BLOCKS, 256>>>(x, out);
}

// round 11
// speedup vs baseline: 1.1334x; 1.0269x over previous
#include <cuda_runtime.h>
#include <cuda_bf16.h>
#include <cstdint>

// x[N=32768, D=2048] fp32 row-major.
// u[d] = sum_n x[n][d]^2 + eps ; out = x * rsqrt(u)
// 3 launches: colsq -> reduce(+rsqrt) -> scale.

#define NROWS 32768
#define NCOLS 2048
#define NCOLS4 512                             // float4 column-groups per row
#define ROWS_PER_CHUNK 32
#define ROW_CHUNKS (NROWS / ROWS_PER_CHUNK)    // 1024
#define KEEP_CHUNK 640                         // tail chunks cached normally
#define EPS 1e-6f

// Deterministic scratch (no atomics anywhere)
__device__ float g_part [ROW_CHUNKS * NCOLS];  // 8 MB
__device__ float g_scale[NCOLS];               // 8 KB

// ---------------------------------------------------------------------------
// K1: per-row-chunk column sum of squares. grid = (2, 1024), 32 rows/chunk.
// (Measured best: 42.0us, 83% DRAM.)
// ---------------------------------------------------------------------------
__global__ void __launch_bounds__(256) colsq_kernel(const float4* __restrict__ x) {
    const int cg    = blockIdx.x * 256 + threadIdx.x;   // 0..511
    const int chunk = blockIdx.y;                        // 0..1023

    const float4* p = x + (size_t)chunk * ROWS_PER_CHUNK * NCOLS4 + cg;

    float ax = 0.f, ay = 0.f, az = 0.f, aw = 0.f;
    if (chunk < KEEP_CHUNK) {
#pragma unroll 8
        for (int r = 0; r < ROWS_PER_CHUNK; ++r) {
            float4 v = __ldcs(p + (size_t)r * NCOLS4);
            ax = fmaf(v.x, v.x, ax);
            ay = fmaf(v.y, v.y, ay);
            az = fmaf(v.z, v.z, az);
            aw = fmaf(v.w, v.w, aw);
        }
    } else {
#pragma unroll 8
        for (int r = 0; r < ROWS_PER_CHUNK; ++r) {
            float4 v = __ldg(p + (size_t)r * NCOLS4);
            ax = fmaf(v.x, v.x, ax);
            ay = fmaf(v.y, v.y, ay);
            az = fmaf(v.z, v.z, az);
            aw = fmaf(v.w, v.w, aw);
        }
    }

    reinterpret_cast<float4*>(g_part)[(size_t)chunk * NCOLS4 + cg] =
        make_float4(ax, ay, az, aw);
}

// ---------------------------------------------------------------------------
// K2: fold 1024 chunk-partials -> scale, high-MLP version.
// 256 CTAs x 8 warps = 2048 warps. Each CTA owns 2 column-groups; 4 warps
// per cg, each folding a 256-chunk quarter (8-iter lane-strided loop ->
// 8 outstanding 16B loads per warp; ~256KB in flight grid-wide).
// Butterfly within warp, smem combine across the 4 warps, rsqrt.
// ---------------------------------------------------------------------------
__global__ void __launch_bounds__(256) reduce_kernel() {
    const int w       = threadIdx.x >> 5;        // warp 0..7
    const int lane    = threadIdx.x & 31;
    const int cg_loc  = w >> 2;                  // 0..1: which cg in this CTA
    const int quarter = w & 3;                   // 0..3: chunk quarter
    const int cg      = blockIdx.x * 2 + cg_loc; // 0..511

    const float4* pp = reinterpret_cast<const float4*>(g_part);
    float4 a = make_float4(0.f, 0.f, 0.f, 0.f);
#pragma unroll
    for (int i = 0; i < 8; ++i) {
        const int k = quarter * 256 + i * 32 + lane;
        float4 v = pp[(size_t)k * NCOLS4 + cg];
        a.x += v.x; a.y += v.y; a.z += v.z; a.w += v.w;
    }
#pragma unroll
    for (int off = 16; off > 0; off >>= 1) {
        a.x += __shfl_xor_sync(0xffffffffu, a.x, off);
        a.y += __shfl_xor_sync(0xffffffffu, a.y, off);
        a.z += __shfl_xor_sync(0xffffffffu, a.z, off);
        a.w += __shfl_xor_sync(0xffffffffu, a.w, off);
    }

    __shared__ float4 s_acc[8];                  // one slot per warp
    if (lane == 0) s_acc[w] = a;
    __syncthreads();

    if (threadIdx.x < 2) {                       // one thread per cg
        float4 q0 = s_acc[threadIdx.x * 4 + 0];
        float4 q1 = s_acc[threadIdx.x * 4 + 1];
        float4 q2 = s_acc[threadIdx.x * 4 + 2];
        float4 q3 = s_acc[threadIdx.x * 4 + 3];
        float4 s;
        s.x = rsqrtf(q0.x + q1.x + q2.x + q3.x + EPS);
        s.y = rsqrtf(q0.y + q1.y + q2.y + q3.y + EPS);
        s.z = rsqrtf(q0.z + q1.z + q2.z + q3.z + EPS);
        s.w = rsqrtf(q0.w + q1.w + q2.w + q3.w + EPS);
        reinterpret_cast<float4*>(g_scale)[blockIdx.x * 2 + threadIdx.x] = s;
    }
}

// ---------------------------------------------------------------------------
// K3: out = x * scale[col]. Measured-best form — simple 4-iter loop, plain
// cached loads, streaming stores, reversed block order.
// ---------------------------------------------------------------------------
#define FL4_TOTAL (NROWS * NCOLS4)             // 16M float4
#define FL4_PER_BLOCK 1024
#define K3_BLOCKS (FL4_TOTAL / FL4_PER_BLOCK)  // 16384

__global__ void __launch_bounds__(256) scale_kernel(const float4* __restrict__ x,
                                                    float4* __restrict__ out) {
    const int blk     = K3_BLOCKS - 1 - blockIdx.x;       // reversed
    const size_t base = (size_t)blk * FL4_PER_BLOCK + threadIdx.x;

#pragma unroll
    for (int it = 0; it < 4; ++it) {
        const size_t i  = base + (size_t)it * 256;
        const int    cg = (int)(i & (NCOLS4 - 1));         // NCOLS4=512 pow2

        float4 s = __ldg(reinterpret_cast<const float4*>(g_scale) + cg);
        float4 v = x[i];
        v.x *= s.x; v.y *= s.y; v.z *= s.z; v.w *= s.w;
        __stcs(out + i, v);
    }
}

// ---------------------------------------------------------------------------
extern "C" void kernel_launch(void* const* d_in, const int* in_sizes, int n_in,
                              void* d_out, int out_size) {
    const float4* x   = reinterpret_cast<const float4*>(d_in[0]);
    float4*       out = reinterpret_cast<float4*>(d_out);

    colsq_kernel <<<dim3(2, ROW_CHUNKS), 256>>>(x);
    reduce_kernel<<<256, 256>>>();
    scale_kernel <<<K3_BLOCKS, 256>>>(x, out);
}